// round 5
// baseline (speedup 1.0000x reference)
#include <cuda_runtime.h>
#include <cuda_fp16.h>
#include <cstdint>
#include <cstddef>

// ---------------------------------------------------------------------------
// WL2 graph conv layer — tf32 mma.sync + fp16 gather buffer:
//   Phase 0: transpose+tf32-round W's; zero conv accumulator
//   Phase 1: XW_n = X @ W_n          (mma.sync tf32 -> g_xwnh, fp16 storage)
//   Phase 2: edge gather/relu/scatter, 2 passes split by backref range so the
//            L2 working set (fp16 xwn 51MB + conv half 51MB) fits in 126MB L2
//   Phase 3: out = relu(X@W_l + (X@W_f)*conv + b)  (dual-GEMM fused epilogue)
// ---------------------------------------------------------------------------

#define NMAX 200000
#define MAXELEMS ((size_t)NMAX * 128)

__device__ __half g_xwnh[MAXELEMS];     // fp16 neighbor projection (gathered)
__device__ float  g_conv[MAXELEMS];     // fp32 scatter accumulator
__device__ float  g_wt[3 * 128 * 128];  // W^T (K-major), tf32-rounded

// ---------------- helpers ----------------
__device__ __forceinline__ uint32_t f2tf32(float x) {
    uint32_t r;
    asm("cvt.rna.tf32.f32 %0, %1;" : "=r"(r) : "f"(x));
    return r;
}

__device__ __forceinline__ void mma_tf32(float* c,
                                         uint32_t a0, uint32_t a1, uint32_t a2, uint32_t a3,
                                         uint32_t b0, uint32_t b1) {
    asm volatile(
        "mma.sync.aligned.m16n8k8.row.col.f32.tf32.tf32.f32 "
        "{%0,%1,%2,%3}, {%4,%5,%6,%7}, {%8,%9}, {%0,%1,%2,%3};"
        : "+f"(c[0]), "+f"(c[1]), "+f"(c[2]), "+f"(c[3])
        : "r"(a0), "r"(a1), "r"(a2), "r"(a3), "r"(b0), "r"(b1));
}

// Padded smem tile: 128 rows x 132 floats. Fragment LDS bank = lane (conflict-free).
#define TPITCH 132
#define TILE_FLOATS (128 * TPITCH)   // 16896 floats = 67584 B

// ---------------------------------------------------------------------------
// Phase 0a: W^T + tf32 rounding
// ---------------------------------------------------------------------------
__global__ void prep_w_kernel(const float* __restrict__ Wl,
                              const float* __restrict__ Wf,
                              const float* __restrict__ Wn) {
    const float* src = (blockIdx.x == 0) ? Wl : ((blockIdx.x == 1) ? Wf : Wn);
    float* dst = g_wt + blockIdx.x * 16384;
    for (int i = threadIdx.x; i < 16384; i += blockDim.x) {
        int n = i >> 7, k = i & 127;
        dst[i] = __uint_as_float(f2tf32(src[k * 128 + n]));
    }
}

// ---------------------------------------------------------------------------
// Phase 0b: zero conv accumulator
// ---------------------------------------------------------------------------
__global__ void zero_conv_kernel(int n4) {
    int i = blockIdx.x * blockDim.x + threadIdx.x;
    if (i < n4) reinterpret_cast<float4*>(g_conv)[i] = make_float4(0.f, 0.f, 0.f, 0.f);
}

// ---------------------------------------------------------------------------
// Tile loaders (512 threads): A from X (with tf32 rounding), B from g_wt.
// ---------------------------------------------------------------------------
__device__ __forceinline__ void load_a_tile(float* As, const float* __restrict__ X,
                                            int row_base, int nrows, int tid) {
    for (int i = tid; i < 4096; i += 512) {
        const int r = i >> 5, c4 = i & 31;
        float4 v = make_float4(0.f, 0.f, 0.f, 0.f);
        if (row_base + r < nrows)
            v = reinterpret_cast<const float4*>(X)[(size_t)(row_base + r) * 32 + c4];
        v.x = __uint_as_float(f2tf32(v.x));
        v.y = __uint_as_float(f2tf32(v.y));
        v.z = __uint_as_float(f2tf32(v.z));
        v.w = __uint_as_float(f2tf32(v.w));
        *reinterpret_cast<float4*>(&As[r * TPITCH + c4 * 4]) = v;
    }
}

__device__ __forceinline__ void load_b_tile(float* Bs, const float* __restrict__ Wt,
                                            int tid) {
    for (int i = tid; i < 4096; i += 512) {
        const int r = i >> 5, c4 = i & 31;
        float4 v = reinterpret_cast<const float4*>(Wt)[i];
        *reinterpret_cast<float4*>(&Bs[r * TPITCH + c4 * 4]) = v;
    }
}

// ---------------------------------------------------------------------------
// Phase 1: XW_n = X @ W_n, fp16 output.  512 threads; warp tile 16 x 64.
// ---------------------------------------------------------------------------
__global__ __launch_bounds__(512, 1)
void gemm_xwn_kernel(const float* __restrict__ X, int nrows) {
    extern __shared__ __align__(16) float smem[];
    float* As = smem;
    float* Bs = smem + TILE_FLOATS;

    const int tid = threadIdx.x;
    const int row_base = blockIdx.x * 128;

    load_a_tile(As, X, row_base, nrows, tid);
    load_b_tile(Bs, g_wt + 2 * 16384, tid);
    __syncthreads();

    const int wid = tid >> 5, lane = tid & 31;
    const int g = lane >> 2, t = lane & 3;
    const int m_base = (wid & 7) * 16;
    const int n_base = (wid >> 3) * 64;

    float acc[8][4];
#pragma unroll
    for (int nt = 0; nt < 8; nt++)
#pragma unroll
        for (int j = 0; j < 4; j++) acc[nt][j] = 0.f;

    const float* ar0 = &As[(m_base + g) * TPITCH + t];
    const float* ar1 = &As[(m_base + 8 + g) * TPITCH + t];
    const float* br  = &Bs[(n_base + g) * TPITCH + t];

#pragma unroll
    for (int ks = 0; ks < 16; ks++) {
        const int k = ks * 8;
        const uint32_t a0 = __float_as_uint(ar0[k]);
        const uint32_t a1 = __float_as_uint(ar1[k]);
        const uint32_t a2 = __float_as_uint(ar0[k + 4]);
        const uint32_t a3 = __float_as_uint(ar1[k + 4]);
#pragma unroll
        for (int nt = 0; nt < 8; nt++) {
            const uint32_t b0 = __float_as_uint(br[nt * 8 * TPITCH + k]);
            const uint32_t b1 = __float_as_uint(br[nt * 8 * TPITCH + k + 4]);
            mma_tf32(acc[nt], a0, a1, a2, a3, b0, b1);
        }
    }

    const int r0 = row_base + m_base + g;
    const int r1 = r0 + 8;
#pragma unroll
    for (int nt = 0; nt < 8; nt++) {
        const int col = n_base + nt * 8 + 2 * t;
        if (r0 < nrows)
            *reinterpret_cast<__half2*>(g_xwnh + (size_t)r0 * 128 + col) =
                __floats2half2_rn(acc[nt][0], acc[nt][1]);
        if (r1 < nrows)
            *reinterpret_cast<__half2*>(g_xwnh + (size_t)r1 * 128 + col) =
                __floats2half2_rn(acc[nt][2], acc[nt][3]);
    }
}

// ---------------------------------------------------------------------------
// Phase 2: edge gather/relu/scatter. One warp per edge, lane = 4 units (fp16
// gather, fp32 math + atomics). Only edges whose backref falls in [lo,hi)
// are processed — callers sweep the conv range so each pass's L2 set fits.
// ---------------------------------------------------------------------------
__global__ __launch_bounds__(256)
void edge_kernel(const int* __restrict__ ra, const int* __restrict__ rb,
                 const int* __restrict__ br, const float* __restrict__ bn,
                 int m, int lo, int hi) {
    const int e = blockIdx.x * 8 + (threadIdx.x >> 5);
    if (e >= m) return;

    const int c = __ldg(br + e);
    if (c < lo || c >= hi) return;

    const int lane = threadIdx.x & 31;
    const int a = __ldg(ra + e);
    const int b = __ldg(rb + e);

    // 4 halves per lane = 8 bytes; a row is 256B, fully coalesced per warp.
    const uint2 pa = *reinterpret_cast<const uint2*>(g_xwnh + (size_t)a * 128 + lane * 4);
    const uint2 pb = *reinterpret_cast<const uint2*>(g_xwnh + (size_t)b * 128 + lane * 4);
    const float2 a01 = __half22float2(*reinterpret_cast<const __half2*>(&pa.x));
    const float2 a23 = __half22float2(*reinterpret_cast<const __half2*>(&pa.y));
    const float2 b01 = __half22float2(*reinterpret_cast<const __half2*>(&pb.x));
    const float2 b23 = __half22float2(*reinterpret_cast<const __half2*>(&pb.y));
    const float4 bb = __ldg(reinterpret_cast<const float4*>(bn) + lane);

    const float x = fmaxf(a01.x + b01.x + bb.x, 0.f);
    const float y = fmaxf(a01.y + b01.y + bb.y, 0.f);
    const float z = fmaxf(a23.x + b23.x + bb.z, 0.f);
    const float w = fmaxf(a23.y + b23.y + bb.w, 0.f);

    float* dst = g_conv + (size_t)c * 128 + lane * 4;
    asm volatile("red.global.add.v4.f32 [%0], {%1, %2, %3, %4};"
                 :: "l"(dst), "f"(x), "f"(y), "f"(z), "f"(w) : "memory");
}

// ---------------------------------------------------------------------------
// Phase 3: fused final: dual GEMM (W_local, W_filter) + epilogue.
// out = relu(Dl + Df * conv + b)
// ---------------------------------------------------------------------------
__global__ __launch_bounds__(512, 1)
void gemm_final_kernel(const float* __restrict__ X, const float* __restrict__ b,
                       float* __restrict__ out, int nrows) {
    extern __shared__ __align__(16) float smem[];
    float* As  = smem;
    float* Bsl = smem + TILE_FLOATS;
    float* Bsf = smem + 2 * TILE_FLOATS;

    const int tid = threadIdx.x;
    const int row_base = blockIdx.x * 128;

    load_a_tile(As, X, row_base, nrows, tid);
    load_b_tile(Bsl, g_wt + 0 * 16384, tid);
    load_b_tile(Bsf, g_wt + 1 * 16384, tid);
    __syncthreads();

    const int wid = tid >> 5, lane = tid & 31;
    const int g = lane >> 2, t = lane & 3;
    const int m_base = (wid & 7) * 16;
    const int n_base = (wid >> 3) * 64;

    float accl[8][4], accf[8][4];
#pragma unroll
    for (int nt = 0; nt < 8; nt++)
#pragma unroll
        for (int j = 0; j < 4; j++) { accl[nt][j] = 0.f; accf[nt][j] = 0.f; }

    const float* ar0 = &As[(m_base + g) * TPITCH + t];
    const float* ar1 = &As[(m_base + 8 + g) * TPITCH + t];
    const float* brl = &Bsl[(n_base + g) * TPITCH + t];
    const float* brf = &Bsf[(n_base + g) * TPITCH + t];

#pragma unroll
    for (int ks = 0; ks < 16; ks++) {
        const int k = ks * 8;
        const uint32_t a0 = __float_as_uint(ar0[k]);
        const uint32_t a1 = __float_as_uint(ar1[k]);
        const uint32_t a2 = __float_as_uint(ar0[k + 4]);
        const uint32_t a3 = __float_as_uint(ar1[k + 4]);
#pragma unroll
        for (int nt = 0; nt < 8; nt++) {
            const uint32_t bl0 = __float_as_uint(brl[nt * 8 * TPITCH + k]);
            const uint32_t bl1 = __float_as_uint(brl[nt * 8 * TPITCH + k + 4]);
            mma_tf32(accl[nt], a0, a1, a2, a3, bl0, bl1);
            const uint32_t bf0 = __float_as_uint(brf[nt * 8 * TPITCH + k]);
            const uint32_t bf1 = __float_as_uint(brf[nt * 8 * TPITCH + k + 4]);
            mma_tf32(accf[nt], a0, a1, a2, a3, bf0, bf1);
        }
    }

    const int r0 = row_base + m_base + g;
    const int r1 = r0 + 8;
#pragma unroll
    for (int nt = 0; nt < 8; nt++) {
        const int col = n_base + nt * 8 + 2 * t;
        const float2 b2 = __ldg(reinterpret_cast<const float2*>(b + col));
        if (r0 < nrows) {
            const float2 cv = *reinterpret_cast<const float2*>(g_conv + (size_t)r0 * 128 + col);
            float2 o;
            o.x = fmaxf(fmaf(accf[nt][0], cv.x, accl[nt][0]) + b2.x, 0.f);
            o.y = fmaxf(fmaf(accf[nt][1], cv.y, accl[nt][1]) + b2.y, 0.f);
            *reinterpret_cast<float2*>(out + (size_t)r0 * 128 + col) = o;
        }
        if (r1 < nrows) {
            const float2 cv = *reinterpret_cast<const float2*>(g_conv + (size_t)r1 * 128 + col);
            float2 o;
            o.x = fmaxf(fmaf(accf[nt][2], cv.x, accl[nt][2]) + b2.x, 0.f);
            o.y = fmaxf(fmaf(accf[nt][3], cv.y, accl[nt][3]) + b2.y, 0.f);
            *reinterpret_cast<float2*>(out + (size_t)r1 * 128 + col) = o;
        }
    }
}

// ---------------------------------------------------------------------------
extern "C" void kernel_launch(void* const* d_in, const int* in_sizes, int n_in,
                              void* d_out, int out_size) {
    const float* X  = (const float*)d_in[0];
    const int*   ra = (const int*)d_in[1];
    const int*   rb = (const int*)d_in[2];
    const int*   br = (const int*)d_in[3];
    const float* Wl = (const float*)d_in[4];
    const float* Wf = (const float*)d_in[5];
    const float* Wn = (const float*)d_in[6];
    const float* b  = (const float*)d_in[7];
    const float* bn = (const float*)d_in[8];
    float* out = (float*)d_out;

    const int n  = in_sizes[0] / 128;   // 200000
    const int m  = in_sizes[1];         // 2000000
    const int n4 = n * 32;
    const int ntiles = (n + 127) / 128;

    const int smem_a = 2 * TILE_FLOATS * 4;   // 135168 B
    const int smem_c = 3 * TILE_FLOATS * 4;   // 202752 B

    static bool attr_done = false;
    if (!attr_done) {
        cudaFuncSetAttribute(gemm_xwn_kernel,
                             cudaFuncAttributeMaxDynamicSharedMemorySize, smem_a);
        cudaFuncSetAttribute(gemm_final_kernel,
                             cudaFuncAttributeMaxDynamicSharedMemorySize, smem_c);
        attr_done = true;
    }

    prep_w_kernel<<<3, 256>>>(Wl, Wf, Wn);
    zero_conv_kernel<<<(n4 + 255) / 256, 256>>>(n4);
    gemm_xwn_kernel<<<ntiles, 512, smem_a>>>(X, n);

    // Two passes over the edges, split by destination (backref) range so the
    // per-pass L2 working set (xwn fp16 51MB + conv half 51MB) fits in L2.
    const int half = n / 2;
    edge_kernel<<<(m + 7) / 8, 256>>>(ra, rb, br, bn, m, 0, half);
    edge_kernel<<<(m + 7) / 8, 256>>>(ra, rb, br, bn, m, half, n);

    gemm_final_kernel<<<ntiles, 512, smem_c>>>(X, b, out, n);
}

// round 6
// speedup vs baseline: 1.9468x; 1.9468x over previous
#include <cuda_runtime.h>
#include <cuda_fp16.h>
#include <cstdint>
#include <cstddef>

// ---------------------------------------------------------------------------
// WL2 graph conv layer — tf32 mma.sync, persistent pipelined GEMMs,
// multi-edge-per-warp L2-resident edge phase.
//   Phase 0: transpose+tf32-round W's; zero conv accumulator
//   Phase 1: XW_n = X @ W_n    (persistent, cp.async double-buffered, fp16 out)
//   Phase 2: edge gather/relu/scatter, 2 passes split by backref range
//            (working set fp16-xwn 51MB + conv-half 51MB fits 126MB L2),
//            32 edges/warp with 4-deep gather pipeline
//   Phase 3: out = relu(X@W_l + (X@W_f)*conv + b)  (persistent dual GEMM)
// ---------------------------------------------------------------------------

#define NMAX 200000
#define MAXELEMS ((size_t)NMAX * 128)

__device__ __half g_xwnh[MAXELEMS];     // fp16 neighbor projection (gathered)
__device__ float  g_conv[MAXELEMS];     // fp32 scatter accumulator
__device__ float  g_wt[3 * 128 * 128];  // W^T (K-major), tf32-rounded

// ---------------- helpers ----------------
__device__ __forceinline__ uint32_t f2tf32(float x) {
    uint32_t r;
    asm("cvt.rna.tf32.f32 %0, %1;" : "=r"(r) : "f"(x));
    return r;
}

__device__ __forceinline__ uint32_t smem_u32(const void* p) {
    uint32_t a;
    asm("{ .reg .u64 t; cvta.to.shared.u64 t, %1; cvt.u32.u64 %0, t; }"
        : "=r"(a) : "l"(p));
    return a;
}

__device__ __forceinline__ void cp_async16(uint32_t dst, const void* src) {
    asm volatile("cp.async.ca.shared.global [%0], [%1], 16;"
                 :: "r"(dst), "l"(src) : "memory");
}
__device__ __forceinline__ void cp_commit() {
    asm volatile("cp.async.commit_group;" ::: "memory");
}
__device__ __forceinline__ void cp_wait1() {
    asm volatile("cp.async.wait_group 1;" ::: "memory");
}

__device__ __forceinline__ void mma_tf32(float* c,
                                         uint32_t a0, uint32_t a1, uint32_t a2, uint32_t a3,
                                         uint32_t b0, uint32_t b1) {
    asm volatile(
        "mma.sync.aligned.m16n8k8.row.col.f32.tf32.tf32.f32 "
        "{%0,%1,%2,%3}, {%4,%5,%6,%7}, {%8,%9}, {%0,%1,%2,%3};"
        : "+f"(c[0]), "+f"(c[1]), "+f"(c[2]), "+f"(c[3])
        : "r"(a0), "r"(a1), "r"(a2), "r"(a3), "r"(b0), "r"(b1));
}

// Padded smem tiles: pitch 132 floats -> fragment LDS conflict-free.
#define TPITCH 132
#define TILE_FLOATS (128 * TPITCH)     // full 128-row tile (B operands)

// ---------------------------------------------------------------------------
// Phase 0a: W^T + tf32 rounding
// ---------------------------------------------------------------------------
__global__ void prep_w_kernel(const float* __restrict__ Wl,
                              const float* __restrict__ Wf,
                              const float* __restrict__ Wn) {
    const float* src = (blockIdx.x == 0) ? Wl : ((blockIdx.x == 1) ? Wf : Wn);
    float* dst = g_wt + blockIdx.x * 16384;
    for (int i = threadIdx.x; i < 16384; i += blockDim.x) {
        int n = i >> 7, k = i & 127;
        dst[i] = __uint_as_float(f2tf32(src[k * 128 + n]));
    }
}

// ---------------------------------------------------------------------------
// Phase 0b: zero conv accumulator
// ---------------------------------------------------------------------------
__global__ void zero_conv_kernel(int n4) {
    int i = blockIdx.x * blockDim.x + threadIdx.x;
    if (i < n4) reinterpret_cast<float4*>(g_conv)[i] = make_float4(0.f, 0.f, 0.f, 0.f);
}

// B-tile loader (raw fp32, already tf32-rounded in g_wt)
__device__ __forceinline__ void load_b_tile(float* Bs, const float* __restrict__ Wt,
                                            int tid) {
    for (int i = tid; i < 4096; i += 512) {
        const int r = i >> 5, c4 = i & 31;
        float4 v = reinterpret_cast<const float4*>(Wt)[i];
        *reinterpret_cast<float4*>(&Bs[r * TPITCH + c4 * 4]) = v;
    }
}

// ---------------------------------------------------------------------------
// Phase 1: XW_n = X @ W_n, persistent; 64-row chunks, double-buffered A.
// 16 warps: m-group = wid&3 (16 rows), n-group = wid>>2 (32 cols).
// ---------------------------------------------------------------------------
#define XC_ROWS 64
#define XC_FLOATS (XC_ROWS * TPITCH)

__global__ __launch_bounds__(512, 1)
void gemm_xwn_kernel(const float* __restrict__ X, int nrows) {
    extern __shared__ __align__(16) float smem[];
    float* Bs = smem;                       // [128][TPITCH]
    float* Ab[2] = { smem + TILE_FLOATS, smem + TILE_FLOATS + XC_FLOATS };
    const uint32_t sb = smem_u32(smem);
    const uint32_t aoff[2] = { (uint32_t)(TILE_FLOATS * 4),
                               (uint32_t)((TILE_FLOATS + XC_FLOATS) * 4) };

    const int tid = threadIdx.x;
    const int ntiles = (nrows + XC_ROWS - 1) / XC_ROWS;
    const int stride = gridDim.x;

    load_b_tile(Bs, g_wt + 2 * 16384, tid);

    // Prefetch first chunk
    int tile0 = blockIdx.x;
    if (tile0 < ntiles) {
#pragma unroll
        for (int j = 0; j < 4; j++) {
            const int i = tid + j * 512;
            const int r = i >> 5, c4 = i & 31;
            const int gr = tile0 * XC_ROWS + r;
            if (gr < nrows)
                cp_async16(sb + aoff[0] + (uint32_t)(r * TPITCH + c4 * 4) * 4,
                           X + (size_t)gr * 128 + c4 * 4);
        }
    }
    cp_commit();

    const int wid = tid >> 5, lane = tid & 31;
    const int g = lane >> 2, t = lane & 3;
    const int m_base = (wid & 3) * 16;
    const int n_base = (wid >> 2) * 32;

    int buf = 0;
    for (int tile = tile0; tile < ntiles; tile += stride, buf ^= 1) {
        // Prefetch next chunk into other buffer
        const int nxt = tile + stride;
        if (nxt < ntiles) {
#pragma unroll
            for (int j = 0; j < 4; j++) {
                const int i = tid + j * 512;
                const int r = i >> 5, c4 = i & 31;
                const int gr = nxt * XC_ROWS + r;
                if (gr < nrows)
                    cp_async16(sb + aoff[buf ^ 1] + (uint32_t)(r * TPITCH + c4 * 4) * 4,
                               X + (size_t)gr * 128 + c4 * 4);
            }
        }
        cp_commit();
        cp_wait1();          // current chunk resident
        __syncthreads();

        const float* As = Ab[buf];
        float acc[4][4];
#pragma unroll
        for (int nt = 0; nt < 4; nt++)
#pragma unroll
            for (int j = 0; j < 4; j++) acc[nt][j] = 0.f;

        const float* ar0 = &As[(m_base + g) * TPITCH + t];
        const float* ar1 = &As[(m_base + 8 + g) * TPITCH + t];
        const float* br  = &Bs[(n_base + g) * TPITCH + t];

#pragma unroll
        for (int ks = 0; ks < 16; ks++) {
            const int k = ks * 8;
            const uint32_t a0 = f2tf32(ar0[k]);
            const uint32_t a1 = f2tf32(ar1[k]);
            const uint32_t a2 = f2tf32(ar0[k + 4]);
            const uint32_t a3 = f2tf32(ar1[k + 4]);
#pragma unroll
            for (int nt = 0; nt < 4; nt++) {
                const uint32_t b0 = __float_as_uint(br[nt * 8 * TPITCH + k]);
                const uint32_t b1 = __float_as_uint(br[nt * 8 * TPITCH + k + 4]);
                mma_tf32(acc[nt], a0, a1, a2, a3, b0, b1);
            }
        }

        const int r0 = tile * XC_ROWS + m_base + g;
        const int r1 = r0 + 8;
#pragma unroll
        for (int nt = 0; nt < 4; nt++) {
            const int col = n_base + nt * 8 + 2 * t;
            if (r0 < nrows)
                *reinterpret_cast<__half2*>(g_xwnh + (size_t)r0 * 128 + col) =
                    __floats2half2_rn(acc[nt][0], acc[nt][1]);
            if (r1 < nrows)
                *reinterpret_cast<__half2*>(g_xwnh + (size_t)r1 * 128 + col) =
                    __floats2half2_rn(acc[nt][2], acc[nt][3]);
        }
        __syncthreads();   // all warps done with Ab[buf] before it is refilled
    }
}

// ---------------------------------------------------------------------------
// Phase 2: edge gather/relu/scatter. 32 edges per warp, 4-deep gather
// pipeline. Only edges with backref in [lo,hi) are processed.
// ---------------------------------------------------------------------------
__global__ __launch_bounds__(256)
void edge_kernel(const int* __restrict__ ra, const int* __restrict__ rb,
                 const int* __restrict__ br, const float* __restrict__ bn,
                 int m, int lo, int hi) {
    const int wid = threadIdx.x >> 5;
    const int lane = threadIdx.x & 31;
    const int e_base = (blockIdx.x * 8 + wid) * 32;
    if (e_base >= m) return;

    const int e = e_base + lane;
    const bool ev = e < m;
    const int a_l = ev ? __ldg(ra + e) : 0;
    const int b_l = ev ? __ldg(rb + e) : 0;
    const int c_l = ev ? __ldg(br + e) : -1;

    const float4 bb = __ldg(reinterpret_cast<const float4*>(bn) + lane);

#pragma unroll 2
    for (int i = 0; i < 32; i += 4) {
        uint2 pa[4], pb[4];
        int cc[4];
#pragma unroll
        for (int j = 0; j < 4; j++) {
            const int c = __shfl_sync(0xffffffffu, c_l, i + j);
            cc[j] = c;
            if (c >= lo && c < hi) {            // warp-uniform branch
                const int a = __shfl_sync(0xffffffffu, a_l, i + j);
                const int bq = __shfl_sync(0xffffffffu, b_l, i + j);
                pa[j] = *reinterpret_cast<const uint2*>(g_xwnh + (size_t)a * 128 + lane * 4);
                pb[j] = *reinterpret_cast<const uint2*>(g_xwnh + (size_t)bq * 128 + lane * 4);
            }
        }
#pragma unroll
        for (int j = 0; j < 4; j++) {
            if (cc[j] < lo || cc[j] >= hi) continue;
            const float2 a01 = __half22float2(*reinterpret_cast<const __half2*>(&pa[j].x));
            const float2 a23 = __half22float2(*reinterpret_cast<const __half2*>(&pa[j].y));
            const float2 b01 = __half22float2(*reinterpret_cast<const __half2*>(&pb[j].x));
            const float2 b23 = __half22float2(*reinterpret_cast<const __half2*>(&pb[j].y));

            const float x = fmaxf(a01.x + b01.x + bb.x, 0.f);
            const float y = fmaxf(a01.y + b01.y + bb.y, 0.f);
            const float z = fmaxf(a23.x + b23.x + bb.z, 0.f);
            const float w = fmaxf(a23.y + b23.y + bb.w, 0.f);

            float* dst = g_conv + (size_t)cc[j] * 128 + lane * 4;
            asm volatile("red.global.add.v4.f32 [%0], {%1, %2, %3, %4};"
                         :: "l"(dst), "f"(x), "f"(y), "f"(z), "f"(w) : "memory");
        }
    }
}

// ---------------------------------------------------------------------------
// Phase 3: persistent fused final: dual GEMM (W_local, W_filter) + epilogue.
// 32-row chunks, double-buffered A. 16 warps: m-group = wid&1, n-group = wid>>1.
// out = relu(Dl + Df * conv + b)
// ---------------------------------------------------------------------------
#define FC_ROWS 32
#define FC_FLOATS (FC_ROWS * TPITCH)

__global__ __launch_bounds__(512, 1)
void gemm_final_kernel(const float* __restrict__ X, const float* __restrict__ b,
                       float* __restrict__ out, int nrows) {
    extern __shared__ __align__(16) float smem[];
    float* Bsl = smem;
    float* Bsf = smem + TILE_FLOATS;
    float* Ab[2] = { smem + 2 * TILE_FLOATS, smem + 2 * TILE_FLOATS + FC_FLOATS };
    const uint32_t sb = smem_u32(smem);
    const uint32_t aoff[2] = { (uint32_t)(2 * TILE_FLOATS * 4),
                               (uint32_t)((2 * TILE_FLOATS + FC_FLOATS) * 4) };

    const int tid = threadIdx.x;
    const int ntiles = (nrows + FC_ROWS - 1) / FC_ROWS;
    const int stride = gridDim.x;

    load_b_tile(Bsl, g_wt + 0 * 16384, tid);
    load_b_tile(Bsf, g_wt + 1 * 16384, tid);

    int tile0 = blockIdx.x;
    if (tile0 < ntiles) {
#pragma unroll
        for (int j = 0; j < 2; j++) {
            const int i = tid + j * 512;
            const int r = i >> 5, c4 = i & 31;
            const int gr = tile0 * FC_ROWS + r;
            if (gr < nrows)
                cp_async16(sb + aoff[0] + (uint32_t)(r * TPITCH + c4 * 4) * 4,
                           X + (size_t)gr * 128 + c4 * 4);
        }
    }
    cp_commit();

    const int wid = tid >> 5, lane = tid & 31;
    const int g = lane >> 2, t = lane & 3;
    const int m_base = (wid & 1) * 16;
    const int n_base = (wid >> 1) * 16;

    int buf = 0;
    for (int tile = tile0; tile < ntiles; tile += stride, buf ^= 1) {
        const int nxt = tile + stride;
        if (nxt < ntiles) {
#pragma unroll
            for (int j = 0; j < 2; j++) {
                const int i = tid + j * 512;
                const int r = i >> 5, c4 = i & 31;
                const int gr = nxt * FC_ROWS + r;
                if (gr < nrows)
                    cp_async16(sb + aoff[buf ^ 1] + (uint32_t)(r * TPITCH + c4 * 4) * 4,
                               X + (size_t)gr * 128 + c4 * 4);
            }
        }
        cp_commit();
        cp_wait1();
        __syncthreads();

        const float* As = Ab[buf];
        float accl[2][4], accf[2][4];
#pragma unroll
        for (int nt = 0; nt < 2; nt++)
#pragma unroll
            for (int j = 0; j < 4; j++) { accl[nt][j] = 0.f; accf[nt][j] = 0.f; }

        const float* ar0 = &As[(m_base + g) * TPITCH + t];
        const float* ar1 = &As[(m_base + 8 + g) * TPITCH + t];
        const float* brl = &Bsl[(n_base + g) * TPITCH + t];
        const float* brf = &Bsf[(n_base + g) * TPITCH + t];

#pragma unroll
        for (int ks = 0; ks < 16; ks++) {
            const int k = ks * 8;
            const uint32_t a0 = f2tf32(ar0[k]);
            const uint32_t a1 = f2tf32(ar1[k]);
            const uint32_t a2 = f2tf32(ar0[k + 4]);
            const uint32_t a3 = f2tf32(ar1[k + 4]);
#pragma unroll
            for (int nt = 0; nt < 2; nt++) {
                const uint32_t bl0 = __float_as_uint(brl[nt * 8 * TPITCH + k]);
                const uint32_t bl1 = __float_as_uint(brl[nt * 8 * TPITCH + k + 4]);
                mma_tf32(accl[nt], a0, a1, a2, a3, bl0, bl1);
                const uint32_t bf0 = __float_as_uint(brf[nt * 8 * TPITCH + k]);
                const uint32_t bf1 = __float_as_uint(brf[nt * 8 * TPITCH + k + 4]);
                mma_tf32(accf[nt], a0, a1, a2, a3, bf0, bf1);
            }
        }

        const int r0 = tile * FC_ROWS + m_base + g;
        const int r1 = r0 + 8;
#pragma unroll
        for (int nt = 0; nt < 2; nt++) {
            const int col = n_base + nt * 8 + 2 * t;
            const float2 b2 = __ldg(reinterpret_cast<const float2*>(b + col));
            if (r0 < nrows) {
                const float2 cv = *reinterpret_cast<const float2*>(g_conv + (size_t)r0 * 128 + col);
                float2 o;
                o.x = fmaxf(fmaf(accf[nt][0], cv.x, accl[nt][0]) + b2.x, 0.f);
                o.y = fmaxf(fmaf(accf[nt][1], cv.y, accl[nt][1]) + b2.y, 0.f);
                *reinterpret_cast<float2*>(out + (size_t)r0 * 128 + col) = o;
            }
            if (r1 < nrows) {
                const float2 cv = *reinterpret_cast<const float2*>(g_conv + (size_t)r1 * 128 + col);
                float2 o;
                o.x = fmaxf(fmaf(accf[nt][2], cv.x, accl[nt][2]) + b2.x, 0.f);
                o.y = fmaxf(fmaf(accf[nt][3], cv.y, accl[nt][3]) + b2.y, 0.f);
                *reinterpret_cast<float2*>(out + (size_t)r1 * 128 + col) = o;
            }
        }
        __syncthreads();
    }
}

// ---------------------------------------------------------------------------
extern "C" void kernel_launch(void* const* d_in, const int* in_sizes, int n_in,
                              void* d_out, int out_size) {
    const float* X  = (const float*)d_in[0];
    const int*   ra = (const int*)d_in[1];
    const int*   rb = (const int*)d_in[2];
    const int*   br = (const int*)d_in[3];
    const float* Wl = (const float*)d_in[4];
    const float* Wf = (const float*)d_in[5];
    const float* Wn = (const float*)d_in[6];
    const float* b  = (const float*)d_in[7];
    const float* bn = (const float*)d_in[8];
    float* out = (float*)d_out;

    const int n  = in_sizes[0] / 128;   // 200000
    const int m  = in_sizes[1];         // 2000000
    const int n4 = n * 32;

    const int smem_x = (TILE_FLOATS + 2 * XC_FLOATS) * 4;      // 135168 B
    const int smem_f = (2 * TILE_FLOATS + 2 * FC_FLOATS) * 4;  // 168960 B

    static bool attr_done = false;
    if (!attr_done) {
        cudaFuncSetAttribute(gemm_xwn_kernel,
                             cudaFuncAttributeMaxDynamicSharedMemorySize, smem_x);
        cudaFuncSetAttribute(gemm_final_kernel,
                             cudaFuncAttributeMaxDynamicSharedMemorySize, smem_f);
        attr_done = true;
    }

    prep_w_kernel<<<3, 256>>>(Wl, Wf, Wn);
    zero_conv_kernel<<<(n4 + 255) / 256, 256>>>(n4);
    gemm_xwn_kernel<<<148, 512, smem_x>>>(X, n);

    // Two passes over the edges, split by destination (backref) range so the
    // per-pass L2 working set (xwn fp16 51MB + conv half 51MB) stays L2-resident.
    const int half = n / 2;
    const int eblocks = (m + 255) / 256;   // 8 warps x 32 edges per block
    edge_kernel<<<eblocks, 256>>>(ra, rb, br, bn, m, 0, half);
    edge_kernel<<<eblocks, 256>>>(ra, rb, br, bn, m, half, n);

    gemm_final_kernel<<<148, 512, smem_f>>>(X, b, out, n);
}

// round 7
// speedup vs baseline: 2.2688x; 1.1654x over previous
#include <cuda_runtime.h>
#include <cuda_fp16.h>
#include <cstdint>
#include <cstddef>

// ---------------------------------------------------------------------------
// WL2 graph conv layer — tf32 mma.sync GEMMs + counting-sorted gather conv:
//   Phase 0: prep W^T (tf32-rounded)
//   Phase 1: counting sort of edges by backref (hist -> scan -> scatter)
//   Phase 2: XW_n = X @ W_n  (persistent, cp.async double-buffered, fp16 out)
//   Phase 3: conv rows: warp-per-row gather+relu+register-sum, plain stores
//   Phase 4: out = relu(X@W_l + (X@W_f)*conv + b)  (persistent dual GEMM)
// ---------------------------------------------------------------------------

#define NMAX   200000
#define MEDGE  2000000
#define HPAD   200704              // 196 * 1024 (padded histogram length)
#define NBLK   196                 // scan blocks of 1024
#define MAXELEMS ((size_t)NMAX * 128)

__device__ __half g_xwnh[MAXELEMS];      // fp16 neighbor projection
__device__ float  g_conv[MAXELEMS];      // conv rows (written once, no atomics)
__device__ float  g_wt[3 * 128 * 128];   // W^T (K-major), tf32-rounded

__device__ int g_hist[HPAD];
__device__ int g_rowscan[HPAD];
__device__ int g_bsum[NBLK];
__device__ int g_bsumoff[NBLK];
__device__ int g_rowstart[NMAX + 1];
__device__ int g_cursor[NMAX];
__device__ int g_sa[MEDGE];
__device__ int g_sb[MEDGE];

// ---------------- helpers ----------------
__device__ __forceinline__ uint32_t f2tf32(float x) {
    uint32_t r;
    asm("cvt.rna.tf32.f32 %0, %1;" : "=r"(r) : "f"(x));
    return r;
}

__device__ __forceinline__ uint32_t smem_u32(const void* p) {
    uint32_t a;
    asm("{ .reg .u64 t; cvta.to.shared.u64 t, %1; cvt.u32.u64 %0, t; }"
        : "=r"(a) : "l"(p));
    return a;
}

__device__ __forceinline__ void cp_async16(uint32_t dst, const void* src) {
    asm volatile("cp.async.ca.shared.global [%0], [%1], 16;"
                 :: "r"(dst), "l"(src) : "memory");
}
__device__ __forceinline__ void cp_commit() {
    asm volatile("cp.async.commit_group;" ::: "memory");
}
__device__ __forceinline__ void cp_wait1() {
    asm volatile("cp.async.wait_group 1;" ::: "memory");
}

__device__ __forceinline__ void mma_tf32(float* c,
                                         uint32_t a0, uint32_t a1, uint32_t a2, uint32_t a3,
                                         uint32_t b0, uint32_t b1) {
    asm volatile(
        "mma.sync.aligned.m16n8k8.row.col.f32.tf32.tf32.f32 "
        "{%0,%1,%2,%3}, {%4,%5,%6,%7}, {%8,%9}, {%0,%1,%2,%3};"
        : "+f"(c[0]), "+f"(c[1]), "+f"(c[2]), "+f"(c[3])
        : "r"(a0), "r"(a1), "r"(a2), "r"(a3), "r"(b0), "r"(b1));
}

#define TPITCH 132
#define TILE_FLOATS (128 * TPITCH)

// ---------------------------------------------------------------------------
// Phase 0: W^T + tf32 rounding
// ---------------------------------------------------------------------------
__global__ void prep_w_kernel(const float* __restrict__ Wl,
                              const float* __restrict__ Wf,
                              const float* __restrict__ Wn) {
    const float* src = (blockIdx.x == 0) ? Wl : ((blockIdx.x == 1) ? Wf : Wn);
    float* dst = g_wt + blockIdx.x * 16384;
    for (int i = threadIdx.x; i < 16384; i += blockDim.x) {
        int n = i >> 7, k = i & 127;
        dst[i] = __uint_as_float(f2tf32(src[k * 128 + n]));
    }
}

// ---------------------------------------------------------------------------
// Phase 1: counting sort of edges by backref
// ---------------------------------------------------------------------------
__global__ void hist_zero_kernel() {
    int i = blockIdx.x * 256 + threadIdx.x;
    if (i < HPAD) g_hist[i] = 0;
}

__global__ void hist_kernel(const int* __restrict__ br, int m) {
    for (int e = blockIdx.x * 256 + threadIdx.x; e < m; e += gridDim.x * 256)
        atomicAdd(&g_hist[__ldg(br + e)], 1);
}

// Exclusive scan of 1024-int blocks; per-block totals to g_bsum.
__global__ void scan1_kernel() {
    __shared__ int wsum[8];
    const int t = threadIdx.x;
    const int base = blockIdx.x * 1024 + t * 4;
    const int4 v = *reinterpret_cast<const int4*>(g_hist + base);
    const int s1 = v.x + v.y, s2 = s1 + v.z, s3 = s2 + v.w;
    const int lane = t & 31, w = t >> 5;
    int x = s3;
#pragma unroll
    for (int d = 1; d < 32; d <<= 1) {
        int y = __shfl_up_sync(0xffffffffu, x, d);
        if (lane >= d) x += y;
    }
    if (lane == 31) wsum[w] = x;
    __syncthreads();
    if (t < 8) {
        int v2 = wsum[t];
#pragma unroll
        for (int d = 1; d < 8; d <<= 1) {
            int y = __shfl_up_sync(0xffu, v2, d);
            if (t >= d) v2 += y;
        }
        wsum[t] = v2;
    }
    __syncthreads();
    const int woff = w ? wsum[w - 1] : 0;
    const int excl = woff + x - s3;
    int4 o;
    o.x = excl; o.y = excl + v.x; o.z = excl + s1; o.w = excl + s2;
    *reinterpret_cast<int4*>(g_rowscan + base) = o;
    if (t == 255) g_bsum[blockIdx.x] = wsum[7];
}

// Exclusive scan of the NBLK block totals (single block).
__global__ void scan2_kernel() {
    __shared__ int wsum[8];
    const int t = threadIdx.x;
    const int v = (t < NBLK) ? g_bsum[t] : 0;
    const int lane = t & 31, w = t >> 5;
    int x = v;
#pragma unroll
    for (int d = 1; d < 32; d <<= 1) {
        int y = __shfl_up_sync(0xffffffffu, x, d);
        if (lane >= d) x += y;
    }
    if (lane == 31) wsum[w] = x;
    __syncthreads();
    if (t < 8) {
        int v2 = wsum[t];
#pragma unroll
        for (int d = 1; d < 8; d <<= 1) {
            int y = __shfl_up_sync(0xffu, v2, d);
            if (t >= d) v2 += y;
        }
        wsum[t] = v2;
    }
    __syncthreads();
    const int woff = w ? wsum[w - 1] : 0;
    if (t < NBLK) g_bsumoff[t] = woff + x - v;
}

__global__ void scan3_kernel(int n, int m) {
    const int i = blockIdx.x * 256 + threadIdx.x;
    if (i < n) {
        const int val = g_rowscan[i] + g_bsumoff[i >> 10];
        g_rowstart[i] = val;
        g_cursor[i] = val;
    }
    if (i == 0) g_rowstart[n] = m;
}

__global__ void scatter_kernel(const int* __restrict__ ra,
                               const int* __restrict__ rb,
                               const int* __restrict__ br, int m) {
    const int e = blockIdx.x * 256 + threadIdx.x;
    if (e >= m) return;
    const int c = __ldg(br + e);
    const int p = atomicAdd(&g_cursor[c], 1);
    g_sa[p] = __ldg(ra + e);
    g_sb[p] = __ldg(rb + e);
}

// ---------------------------------------------------------------------------
// B-tile loader (raw fp32, already tf32-rounded in g_wt)
// ---------------------------------------------------------------------------
__device__ __forceinline__ void load_b_tile(float* Bs, const float* __restrict__ Wt,
                                            int tid) {
    for (int i = tid; i < 4096; i += 512) {
        const int r = i >> 5, c4 = i & 31;
        float4 v = reinterpret_cast<const float4*>(Wt)[i];
        *reinterpret_cast<float4*>(&Bs[r * TPITCH + c4 * 4]) = v;
    }
}

// ---------------------------------------------------------------------------
// Phase 2: XW_n = X @ W_n, persistent; 128-row chunks, double-buffered A.
// 16 warps: m-group = wid&7 (16 rows), n-group = wid>>3 (64 cols, 8 nt).
// ---------------------------------------------------------------------------
#define XC_ROWS 128
#define XC_FLOATS (XC_ROWS * TPITCH)

__global__ __launch_bounds__(512, 1)
void gemm_xwn_kernel(const float* __restrict__ X, int nrows) {
    extern __shared__ __align__(16) float smem[];
    float* Bs = smem;
    float* Ab[2] = { smem + TILE_FLOATS, smem + TILE_FLOATS + XC_FLOATS };
    const uint32_t sb = smem_u32(smem);
    const uint32_t aoff[2] = { (uint32_t)(TILE_FLOATS * 4),
                               (uint32_t)((TILE_FLOATS + XC_FLOATS) * 4) };

    const int tid = threadIdx.x;
    const int ntiles = (nrows + XC_ROWS - 1) / XC_ROWS;
    const int stride = gridDim.x;

    load_b_tile(Bs, g_wt + 2 * 16384, tid);

    int tile0 = blockIdx.x;
    if (tile0 < ntiles) {
#pragma unroll
        for (int j = 0; j < 8; j++) {
            const int i = tid + j * 512;
            const int r = i >> 5, c4 = i & 31;
            const int gr = tile0 * XC_ROWS + r;
            if (gr < nrows)
                cp_async16(sb + aoff[0] + (uint32_t)(r * TPITCH + c4 * 4) * 4,
                           X + (size_t)gr * 128 + c4 * 4);
        }
    }
    cp_commit();

    const int wid = tid >> 5, lane = tid & 31;
    const int g = lane >> 2, t = lane & 3;
    const int m_base = (wid & 7) * 16;
    const int n_base = (wid >> 3) * 64;

    int buf = 0;
    for (int tile = tile0; tile < ntiles; tile += stride, buf ^= 1) {
        const int nxt = tile + stride;
        if (nxt < ntiles) {
#pragma unroll
            for (int j = 0; j < 8; j++) {
                const int i = tid + j * 512;
                const int r = i >> 5, c4 = i & 31;
                const int gr = nxt * XC_ROWS + r;
                if (gr < nrows)
                    cp_async16(sb + aoff[buf ^ 1] + (uint32_t)(r * TPITCH + c4 * 4) * 4,
                               X + (size_t)gr * 128 + c4 * 4);
            }
        }
        cp_commit();
        cp_wait1();
        __syncthreads();

        const float* As = Ab[buf];
        float acc[8][4];
#pragma unroll
        for (int nt = 0; nt < 8; nt++)
#pragma unroll
            for (int j = 0; j < 4; j++) acc[nt][j] = 0.f;

        const float* ar0 = &As[(m_base + g) * TPITCH + t];
        const float* ar1 = &As[(m_base + 8 + g) * TPITCH + t];
        const float* br  = &Bs[(n_base + g) * TPITCH + t];

#pragma unroll
        for (int ks = 0; ks < 16; ks++) {
            const int k = ks * 8;
            const uint32_t a0 = f2tf32(ar0[k]);
            const uint32_t a1 = f2tf32(ar1[k]);
            const uint32_t a2 = f2tf32(ar0[k + 4]);
            const uint32_t a3 = f2tf32(ar1[k + 4]);
#pragma unroll
            for (int nt = 0; nt < 8; nt++) {
                const uint32_t b0 = __float_as_uint(br[nt * 8 * TPITCH + k]);
                const uint32_t b1 = __float_as_uint(br[nt * 8 * TPITCH + k + 4]);
                mma_tf32(acc[nt], a0, a1, a2, a3, b0, b1);
            }
        }

        const int r0 = tile * XC_ROWS + m_base + g;
        const int r1 = r0 + 8;
#pragma unroll
        for (int nt = 0; nt < 8; nt++) {
            const int col = n_base + nt * 8 + 2 * t;
            if (r0 < nrows)
                *reinterpret_cast<__half2*>(g_xwnh + (size_t)r0 * 128 + col) =
                    __floats2half2_rn(acc[nt][0], acc[nt][1]);
            if (r1 < nrows)
                *reinterpret_cast<__half2*>(g_xwnh + (size_t)r1 * 128 + col) =
                    __floats2half2_rn(acc[nt][2], acc[nt][3]);
        }
        __syncthreads();
    }
}

// ---------------------------------------------------------------------------
// Phase 3: conv rows. One warp per row; gather its edges, relu, accumulate in
// registers, single coalesced store. No atomics, no zero pass.
// ---------------------------------------------------------------------------
__global__ __launch_bounds__(256)
void conv_row_kernel(const float* __restrict__ bn, int n) {
    const int wid = threadIdx.x >> 5, lane = threadIdx.x & 31;
    const int r = blockIdx.x * 8 + wid;
    if (r >= n) return;

    const int s0 = g_rowstart[r];
    const int s1 = g_rowstart[r + 1];
    const float4 bb = __ldg(reinterpret_cast<const float4*>(bn) + lane);

    float ax = 0.f, ay = 0.f, az = 0.f, aw = 0.f;

    int i = s0;
    for (; i + 2 <= s1; i += 2) {
        const int a0 = __ldg(g_sa + i),     b0 = __ldg(g_sb + i);
        const int a1 = __ldg(g_sa + i + 1), b1 = __ldg(g_sb + i + 1);
        const uint2 pa0 = *reinterpret_cast<const uint2*>(g_xwnh + (size_t)a0 * 128 + lane * 4);
        const uint2 pb0 = *reinterpret_cast<const uint2*>(g_xwnh + (size_t)b0 * 128 + lane * 4);
        const uint2 pa1 = *reinterpret_cast<const uint2*>(g_xwnh + (size_t)a1 * 128 + lane * 4);
        const uint2 pb1 = *reinterpret_cast<const uint2*>(g_xwnh + (size_t)b1 * 128 + lane * 4);

        {
            const float2 x01 = __half22float2(*reinterpret_cast<const __half2*>(&pa0.x));
            const float2 x23 = __half22float2(*reinterpret_cast<const __half2*>(&pa0.y));
            const float2 y01 = __half22float2(*reinterpret_cast<const __half2*>(&pb0.x));
            const float2 y23 = __half22float2(*reinterpret_cast<const __half2*>(&pb0.y));
            ax += fmaxf(x01.x + y01.x + bb.x, 0.f);
            ay += fmaxf(x01.y + y01.y + bb.y, 0.f);
            az += fmaxf(x23.x + y23.x + bb.z, 0.f);
            aw += fmaxf(x23.y + y23.y + bb.w, 0.f);
        }
        {
            const float2 x01 = __half22float2(*reinterpret_cast<const __half2*>(&pa1.x));
            const float2 x23 = __half22float2(*reinterpret_cast<const __half2*>(&pa1.y));
            const float2 y01 = __half22float2(*reinterpret_cast<const __half2*>(&pb1.x));
            const float2 y23 = __half22float2(*reinterpret_cast<const __half2*>(&pb1.y));
            ax += fmaxf(x01.x + y01.x + bb.x, 0.f);
            ay += fmaxf(x01.y + y01.y + bb.y, 0.f);
            az += fmaxf(x23.x + y23.x + bb.z, 0.f);
            aw += fmaxf(x23.y + y23.y + bb.w, 0.f);
        }
    }
    if (i < s1) {
        const int a0 = __ldg(g_sa + i), b0 = __ldg(g_sb + i);
        const uint2 pa0 = *reinterpret_cast<const uint2*>(g_xwnh + (size_t)a0 * 128 + lane * 4);
        const uint2 pb0 = *reinterpret_cast<const uint2*>(g_xwnh + (size_t)b0 * 128 + lane * 4);
        const float2 x01 = __half22float2(*reinterpret_cast<const __half2*>(&pa0.x));
        const float2 x23 = __half22float2(*reinterpret_cast<const __half2*>(&pa0.y));
        const float2 y01 = __half22float2(*reinterpret_cast<const __half2*>(&pb0.x));
        const float2 y23 = __half22float2(*reinterpret_cast<const __half2*>(&pb0.y));
        ax += fmaxf(x01.x + y01.x + bb.x, 0.f);
        ay += fmaxf(x01.y + y01.y + bb.y, 0.f);
        az += fmaxf(x23.x + y23.x + bb.z, 0.f);
        aw += fmaxf(x23.y + y23.y + bb.w, 0.f);
    }

    *reinterpret_cast<float4*>(g_conv + (size_t)r * 128 + lane * 4) =
        make_float4(ax, ay, az, aw);
}

// ---------------------------------------------------------------------------
// Phase 4: persistent fused final: dual GEMM + epilogue, 64-row chunks.
// 16 warps: m-group = wid&3 (16 rows), n-group = wid>>2 (32 cols, 4 nt).
// ---------------------------------------------------------------------------
#define FC_ROWS 64
#define FC_FLOATS (FC_ROWS * TPITCH)

__global__ __launch_bounds__(512, 1)
void gemm_final_kernel(const float* __restrict__ X, const float* __restrict__ b,
                       float* __restrict__ out, int nrows) {
    extern __shared__ __align__(16) float smem[];
    float* Bsl = smem;
    float* Bsf = smem + TILE_FLOATS;
    float* Ab[2] = { smem + 2 * TILE_FLOATS, smem + 2 * TILE_FLOATS + FC_FLOATS };
    const uint32_t sb = smem_u32(smem);
    const uint32_t aoff[2] = { (uint32_t)(2 * TILE_FLOATS * 4),
                               (uint32_t)((2 * TILE_FLOATS + FC_FLOATS) * 4) };

    const int tid = threadIdx.x;
    const int ntiles = (nrows + FC_ROWS - 1) / FC_ROWS;
    const int stride = gridDim.x;

    load_b_tile(Bsl, g_wt + 0 * 16384, tid);
    load_b_tile(Bsf, g_wt + 1 * 16384, tid);

    int tile0 = blockIdx.x;
    if (tile0 < ntiles) {
#pragma unroll
        for (int j = 0; j < 4; j++) {
            const int i = tid + j * 512;
            const int r = i >> 5, c4 = i & 31;
            const int gr = tile0 * FC_ROWS + r;
            if (gr < nrows)
                cp_async16(sb + aoff[0] + (uint32_t)(r * TPITCH + c4 * 4) * 4,
                           X + (size_t)gr * 128 + c4 * 4);
        }
    }
    cp_commit();

    const int wid = tid >> 5, lane = tid & 31;
    const int g = lane >> 2, t = lane & 3;
    const int m_base = (wid & 3) * 16;
    const int n_base = (wid >> 2) * 32;

    int buf = 0;
    for (int tile = tile0; tile < ntiles; tile += stride, buf ^= 1) {
        const int nxt = tile + stride;
        if (nxt < ntiles) {
#pragma unroll
            for (int j = 0; j < 4; j++) {
                const int i = tid + j * 512;
                const int r = i >> 5, c4 = i & 31;
                const int gr = nxt * FC_ROWS + r;
                if (gr < nrows)
                    cp_async16(sb + aoff[buf ^ 1] + (uint32_t)(r * TPITCH + c4 * 4) * 4,
                               X + (size_t)gr * 128 + c4 * 4);
            }
        }
        cp_commit();
        cp_wait1();
        __syncthreads();

        const float* As = Ab[buf];
        float accl[4][4], accf[4][4];
#pragma unroll
        for (int nt = 0; nt < 4; nt++)
#pragma unroll
            for (int j = 0; j < 4; j++) { accl[nt][j] = 0.f; accf[nt][j] = 0.f; }

        const float* ar0 = &As[(m_base + g) * TPITCH + t];
        const float* ar1 = &As[(m_base + 8 + g) * TPITCH + t];
        const float* brl = &Bsl[(n_base + g) * TPITCH + t];
        const float* brf = &Bsf[(n_base + g) * TPITCH + t];

#pragma unroll
        for (int ks = 0; ks < 16; ks++) {
            const int k = ks * 8;
            const uint32_t a0 = f2tf32(ar0[k]);
            const uint32_t a1 = f2tf32(ar1[k]);
            const uint32_t a2 = f2tf32(ar0[k + 4]);
            const uint32_t a3 = f2tf32(ar1[k + 4]);
#pragma unroll
            for (int nt = 0; nt < 4; nt++) {
                const uint32_t bl0 = __float_as_uint(brl[nt * 8 * TPITCH + k]);
                const uint32_t bl1 = __float_as_uint(brl[nt * 8 * TPITCH + k + 4]);
                mma_tf32(accl[nt], a0, a1, a2, a3, bl0, bl1);
                const uint32_t bf0 = __float_as_uint(brf[nt * 8 * TPITCH + k]);
                const uint32_t bf1 = __float_as_uint(brf[nt * 8 * TPITCH + k + 4]);
                mma_tf32(accf[nt], a0, a1, a2, a3, bf0, bf1);
            }
        }

        const int r0 = tile * FC_ROWS + m_base + g;
        const int r1 = r0 + 8;
#pragma unroll
        for (int nt = 0; nt < 4; nt++) {
            const int col = n_base + nt * 8 + 2 * t;
            const float2 b2 = __ldg(reinterpret_cast<const float2*>(b + col));
            if (r0 < nrows) {
                const float2 cv = *reinterpret_cast<const float2*>(g_conv + (size_t)r0 * 128 + col);
                float2 o;
                o.x = fmaxf(fmaf(accf[nt][0], cv.x, accl[nt][0]) + b2.x, 0.f);
                o.y = fmaxf(fmaf(accf[nt][1], cv.y, accl[nt][1]) + b2.y, 0.f);
                *reinterpret_cast<float2*>(out + (size_t)r0 * 128 + col) = o;
            }
            if (r1 < nrows) {
                const float2 cv = *reinterpret_cast<const float2*>(g_conv + (size_t)r1 * 128 + col);
                float2 o;
                o.x = fmaxf(fmaf(accf[nt][2], cv.x, accl[nt][2]) + b2.x, 0.f);
                o.y = fmaxf(fmaf(accf[nt][3], cv.y, accl[nt][3]) + b2.y, 0.f);
                *reinterpret_cast<float2*>(out + (size_t)r1 * 128 + col) = o;
            }
        }
        __syncthreads();
    }
}

// ---------------------------------------------------------------------------
extern "C" void kernel_launch(void* const* d_in, const int* in_sizes, int n_in,
                              void* d_out, int out_size) {
    const float* X  = (const float*)d_in[0];
    const int*   ra = (const int*)d_in[1];
    const int*   rb = (const int*)d_in[2];
    const int*   br = (const int*)d_in[3];
    const float* Wl = (const float*)d_in[4];
    const float* Wf = (const float*)d_in[5];
    const float* Wn = (const float*)d_in[6];
    const float* b  = (const float*)d_in[7];
    const float* bn = (const float*)d_in[8];
    float* out = (float*)d_out;

    const int n = in_sizes[0] / 128;   // 200000
    const int m = in_sizes[1];         // 2000000

    const int smem_x = (TILE_FLOATS + 2 * XC_FLOATS) * 4;      // 202752 B
    const int smem_f = (2 * TILE_FLOATS + 2 * FC_FLOATS) * 4;  // 202752 B

    static bool attr_done = false;
    if (!attr_done) {
        cudaFuncSetAttribute(gemm_xwn_kernel,
                             cudaFuncAttributeMaxDynamicSharedMemorySize, smem_x);
        cudaFuncSetAttribute(gemm_final_kernel,
                             cudaFuncAttributeMaxDynamicSharedMemorySize, smem_f);
        attr_done = true;
    }

    prep_w_kernel<<<3, 256>>>(Wl, Wf, Wn);

    // Counting sort of edges by destination row
    hist_zero_kernel<<<(HPAD + 255) / 256, 256>>>();
    hist_kernel<<<1024, 256>>>(br, m);
    scan1_kernel<<<NBLK, 256>>>();
    scan2_kernel<<<1, 256>>>();
    scan3_kernel<<<(n + 256) / 256, 256>>>(n, m);
    scatter_kernel<<<(m + 255) / 256, 256>>>(ra, rb, br, m);

    gemm_xwn_kernel<<<148, 512, smem_x>>>(X, n);
    conv_row_kernel<<<(n + 7) / 8, 256>>>(bn, n);
    gemm_final_kernel<<<148, 512, smem_f>>>(X, b, out, n);
}